// round 7
// baseline (speedup 1.0000x reference)
#include <cuda_runtime.h>
#include <cuda_fp16.h>
#include <math.h>
#include <stdint.h>

#define E 8
#define DM 1024
#define HID 4096
#define MAXN 16384
#define MAXM (MAXN*2)

#define BM 128
#define BN 256
#define BK 32
#define MTILES 20
#define CAPP (MTILES*BM)     // 2560 padded capacity rows per expert

// smem layout (bytes), per stage
#define A_STRIDE 80          // 40 fp16 per A row (32 data + pad), 128 rows
#define B_STRIDE 528         // 264 fp16 per B k-row (256 data + pad), 32 rows
#define OFF_A 0
#define OFF_B 10240
#define STAGE   27136
#define NSTAGE  4
#define SMEM_TOTAL (NSTAGE*STAGE + 1024)

// ---------------- device scratch ----------------
__device__ int    g_cnt[E];
__device__ int    g_bm[E*MAXM];
__device__ float  g_bg[E*MAXM];
__device__ int    g_disp_tok[E*CAPP];
__device__ float  g_disp_g[E*CAPP];
__device__ int    g_kept[E];
__device__ __half g_w1h[(size_t)E*DM*HID];
__device__ __half g_w2h[(size_t)E*HID*DM];
__device__ __half g_xg[(size_t)E*CAPP*DM];
__device__ __half g_h[(size_t)E*CAPP*HID];

// ---------------- helpers ----------------
__device__ __forceinline__ uint32_t smem_u32(const void* p) {
    uint32_t a;
    asm("{ .reg .u64 t; cvta.to.shared.u64 t, %1; cvt.u32.u64 %0, t; }" : "=r"(a) : "l"(p));
    return a;
}
#define CPA(s, g) \
    asm volatile("cp.async.cg.shared.global [%0], [%1], 16;" :: "r"(s), "l"(g))
#define CPA_COMMIT() asm volatile("cp.async.commit_group;" ::: "memory")
#define CPA_WAIT2()  asm volatile("cp.async.wait_group 2;" ::: "memory")

#define LDSM4(r0,r1,r2,r3,addr) \
    asm volatile("ldmatrix.sync.aligned.m8n8.x4.shared.b16 {%0,%1,%2,%3}, [%4];" \
        : "=r"(r0),"=r"(r1),"=r"(r2),"=r"(r3) : "r"(addr))
#define LDSM4T(r0,r1,r2,r3,addr) \
    asm volatile("ldmatrix.sync.aligned.m8n8.x4.trans.shared.b16 {%0,%1,%2,%3}, [%4];" \
        : "=r"(r0),"=r"(r1),"=r"(r2),"=r"(r3) : "r"(addr))

__device__ __forceinline__ void mma16816(float& d0, float& d1, float& d2, float& d3,
                                         uint32_t a0, uint32_t a1, uint32_t a2, uint32_t a3,
                                         uint32_t b0, uint32_t b1) {
    asm volatile("mma.sync.aligned.m16n8k16.row.col.f32.f16.f16.f32 "
                 "{%0,%1,%2,%3}, {%4,%5,%6,%7}, {%8,%9}, {%0,%1,%2,%3};\n"
                 : "+f"(d0), "+f"(d1), "+f"(d2), "+f"(d3)
                 : "r"(a0), "r"(a1), "r"(a2), "r"(a3), "r"(b0), "r"(b1));
}

__device__ __forceinline__ float silu_f(float z) { return z / (1.f + expf(-z)); }

// ---------------- small kernels ----------------
__global__ void zero_cnt_kernel() {
    if (threadIdx.x < E) g_cnt[threadIdx.x] = 0;
}

#define WRS 9   // padded stride (coprime with 32 -> conflict-free LDS)
__global__ void router_kernel(const float* __restrict__ x,
                              const float* __restrict__ Wr,
                              const float* __restrict__ br, int N) {
    __shared__ float sWr[DM*WRS];
    for (int i = threadIdx.x; i < DM*E; i += blockDim.x) {
        int d = i >> 3, e = i & 7;
        sWr[d*WRS + e] = Wr[i];
    }
    __syncthreads();
    int warp = threadIdx.x >> 5, lane = threadIdx.x & 31;
    int tok = blockIdx.x * 8 + warp;
    if (tok >= N) return;
    const float* xr = x + (size_t)tok * DM;
    float acc[E];
#pragma unroll
    for (int e = 0; e < E; e++) acc[e] = 0.f;
    for (int d = lane; d < DM; d += 32) {
        float xv = __ldg(xr + d);
        const float* w = sWr + d*WRS;
#pragma unroll
        for (int e = 0; e < E; e++) acc[e] += xv * w[e];
    }
#pragma unroll
    for (int e = 0; e < E; e++) {
#pragma unroll
        for (int o = 16; o > 0; o >>= 1) acc[e] += __shfl_xor_sync(0xffffffffu, acc[e], o);
    }
    if (lane == 0) {
        float l[E]; float mx = -1e30f;
#pragma unroll
        for (int e = 0; e < E; e++) { l[e] = acc[e] + br[e]; mx = fmaxf(mx, l[e]); }
        float s = 0.f;
#pragma unroll
        for (int e = 0; e < E; e++) { l[e] = expf(l[e] - mx); s += l[e]; }
        int i1 = 0; float p1 = -1.f;
#pragma unroll
        for (int e = 0; e < E; e++) { if (l[e] > p1) { p1 = l[e]; i1 = e; } }
        int i2 = -1; float p2 = -1.f;
#pragma unroll
        for (int e = 0; e < E; e++) { if (e != i1 && l[e] > p2) { p2 = l[e]; i2 = e; } }
        float inv = 1.f / s;
        int m0 = tok * 2;
        int pos = atomicAdd(&g_cnt[i1], 1);
        g_bm[i1*MAXM + pos] = m0;     g_bg[i1*MAXM + pos] = p1 * inv;
        pos = atomicAdd(&g_cnt[i2], 1);
        g_bm[i2*MAXM + pos] = m0 + 1; g_bg[i2*MAXM + pos] = p2 * inv;
    }
}

#define RCH 1024
__global__ void rank_kernel(int cap) {
    __shared__ float sg[RCH];
    __shared__ int   sm[RCH];
    int e = blockIdx.y;
    int cnt = g_cnt[e];
    if (blockIdx.x == 0 && threadIdx.x == 0) g_kept[e] = min(cnt, cap);
    int i = blockIdx.x * blockDim.x + threadIdx.x;
    bool has = (i < cnt);
    float gi = has ? g_bg[e*MAXM + i] : 0.f;
    int   mi = has ? g_bm[e*MAXM + i] : 0;
    int rank = 0;
    for (int j0 = 0; j0 < cnt; j0 += RCH) {
        int nj = min(RCH, cnt - j0);
        __syncthreads();
        for (int j = threadIdx.x; j < nj; j += blockDim.x) {
            sg[j] = g_bg[e*MAXM + j0 + j];
            sm[j] = g_bm[e*MAXM + j0 + j];
        }
        __syncthreads();
        if (has) {
            for (int j = 0; j < nj; j++) {
                float gj = sg[j]; int mj = sm[j];
                rank += (gj > gi) || (gj == gi && mj < mi);
            }
        }
    }
    if (has && rank < cap) {
        g_disp_tok[e*CAPP + rank] = mi >> 1;
        g_disp_g[e*CAPP + rank]   = gi;
    }
}

// weights fp32 -> fp16 (grid-stride over float4)
__global__ void wconv_kernel(const float* __restrict__ W, __half* __restrict__ out, int n4) {
    int i = blockIdx.x * blockDim.x + threadIdx.x;
    int stride = gridDim.x * blockDim.x;
    for (; i < n4; i += stride) {
        float4 v = __ldg(&((const float4*)W)[i]);
        uint32_t h0, h1;
        asm("cvt.rn.f16x2.f32 %0, %1, %2;" : "=r"(h0) : "f"(v.y), "f"(v.x));
        asm("cvt.rn.f16x2.f32 %0, %1, %2;" : "=r"(h1) : "f"(v.w), "f"(v.z));
        uint2 o; o.x = h0; o.y = h1;
        ((uint2*)out)[i] = o;
    }
}

// gather dispatched rows of x -> fp16 plane (zero-filled beyond kept)
__global__ void gather_kernel(const float* __restrict__ x) {
    int e = blockIdx.y;
    int warp = threadIdx.x >> 5, lane = threadIdx.x & 31;
    int r = blockIdx.x * 8 + warp;
    int kept = g_kept[e];
    bool v = r < kept;
    int tok = v ? g_disp_tok[e*CAPP + r] : 0;
    const float* src = x + (size_t)tok * DM;
    size_t dst = (size_t)(e*CAPP + r) * DM;
    for (int d = lane * 4; d < DM; d += 128) {
        float4 val = v ? __ldg((const float4*)(src + d)) : make_float4(0.f,0.f,0.f,0.f);
        uint32_t h0, h1;
        asm("cvt.rn.f16x2.f32 %0, %1, %2;" : "=r"(h0) : "f"(val.y), "f"(val.x));
        asm("cvt.rn.f16x2.f32 %0, %1, %2;" : "=r"(h1) : "f"(val.w), "f"(val.z));
        uint2 oh; oh.x = h0; oh.y = h1;
        *(uint2*)&g_xg[dst + d] = oh;
    }
}

// ---------------- GEMM (fp16 HMMA, cp.async 4-stage pipeline) ----------------
// IS2==0: A = g_xg [*,DM],  B = g_w1h [DM,HID], epi: silu(+b1) -> g_h
// IS2==1: A = g_h [*,HID],  B = g_w2h [HID,DM], epi: (+b2)*g -> atomicAdd Y
template <int KDIM, int NDIM, int IS2>
__global__ void __launch_bounds__(256, 1)
ffn_gemm_kernel(const __half* __restrict__ A, const __half* __restrict__ W,
                const float* __restrict__ Bias, float* __restrict__ Y) {
    extern __shared__ __align__(1024) char smem[];
    const uint32_t su = smem_u32(smem);
    const int tid = threadIdx.x, warp = tid >> 5, lane = tid & 31;
    const int e = blockIdx.z, m0 = blockIdx.y * BM, n0 = blockIdx.x * BN;
    const int kept = g_kept[e];

    int*   stok  = (int*)(smem + NSTAGE*STAGE);
    float* sgate = (float*)(smem + NSTAGE*STAGE + 512);
    if (tid < BM) {
        int r = m0 + tid; bool v = r < kept;
        stok[tid]  = v ? g_disp_tok[e*CAPP + r] : 0;
        sgate[tid] = v ? g_disp_g[e*CAPP + r]   : 0.f;
    }

    // warp tiling: 2 warps along M (64 rows), 4 along N (64 cols)
    const int wm = (warp >> 2) * 64;
    const int wn = (warp & 3) * 64;
    const int q = lane >> 3, rr = lane & 7;
    const int gp = lane >> 2, tg = lane & 3;

    const uint32_t a_base = (uint32_t)((wm + rr + (q & 1) * 8) * A_STRIDE + (q >> 1) * 16);
    const uint32_t b_base = (uint32_t)((rr + (q & 1) * 8) * B_STRIDE + (wn + (q >> 1) * 8) * 2);

    // producer (cp.async) mapping
    const int a_row = tid >> 2, a_kc = tid & 3;       // rows a_row, a_row+64; 16B chunk a_kc
    const int b_row = tid >> 5, b_nc = tid & 31;      // rows b_row + {0,8,16,24}
    const uint32_t a_cs = (uint32_t)(a_row * A_STRIDE + a_kc * 16);
    const uint32_t b_cs = (uint32_t)(b_row * B_STRIDE + b_nc * 16);
    const __half* At = A + (size_t)(e*CAPP + m0 + a_row)*KDIM + a_kc*8;
    const __half* Bt = W + (size_t)e*KDIM*NDIM + (size_t)b_row*NDIM + n0 + b_nc*8;

    float D[4][8][4];
#pragma unroll
    for (int a = 0; a < 4; a++)
#pragma unroll
        for (int b = 0; b < 8; b++)
#pragma unroll
            for (int c = 0; c < 4; c++) D[a][b][c] = 0.f;

    uint32_t Bh[8][2];
    const int KCH = KDIM / BK;

#define ISSUE(KT, SB) do {                                                     \
    const __half* _a = At + (size_t)(KT)*BK;                                   \
    CPA((SB) + OFF_A + a_cs, _a);                                              \
    CPA((SB) + OFF_A + a_cs + 64*A_STRIDE, _a + (size_t)64*KDIM);              \
    const __half* _b = Bt + (size_t)(KT)*BK*NDIM;                              \
    _Pragma("unroll")                                                          \
    for (int j = 0; j < 4; j++)                                                \
        CPA((SB) + OFF_B + b_cs + j*8*B_STRIDE, _b + (size_t)j*8*NDIM);        \
} while (0)

#define LDSMB(kk) do {                                                         \
    _Pragma("unroll")                                                          \
    for (int ntp = 0; ntp < 4; ntp++)                                          \
        LDSM4T(Bh[ntp*2][0],Bh[ntp*2][1],Bh[ntp*2+1][0],Bh[ntp*2+1][1],        \
               sb + OFF_B + b_base + (kk)*16*B_STRIDE + ntp*32);               \
} while (0)
#define MMA_MT(mt, kk) do {                                                    \
    uint32_t Ah0,Ah1,Ah2,Ah3;                                                  \
    LDSM4(Ah0,Ah1,Ah2,Ah3, sb + OFF_A + a_base + (mt)*16*A_STRIDE + (kk)*32);  \
    _Pragma("unroll")                                                          \
    for (int nt = 0; nt < 8; nt++)                                             \
        mma16816(D[mt][nt][0],D[mt][nt][1],D[mt][nt][2],D[mt][nt][3],          \
                 Ah0,Ah1,Ah2,Ah3, Bh[nt][0],Bh[nt][1]);                        \
} while (0)

    // prologue: 3 stages in flight
    ISSUE(0, su + 0*STAGE); CPA_COMMIT();
    ISSUE(1, su + 1*STAGE); CPA_COMMIT();
    ISSUE(2, su + 2*STAGE); CPA_COMMIT();

#pragma unroll 1
    for (int kt = 0; kt < KCH; kt++) {
        CPA_WAIT2();
        __syncthreads();
        const uint32_t sb = su + (uint32_t)(kt & (NSTAGE-1)) * STAGE;
        if (kt + 3 < KCH) ISSUE(kt + 3, su + (uint32_t)((kt + 3) & (NSTAGE-1)) * STAGE);
        CPA_COMMIT();
        LDSMB(0);
        MMA_MT(0,0); MMA_MT(1,0); MMA_MT(2,0); MMA_MT(3,0);
        LDSMB(1);
        MMA_MT(0,1); MMA_MT(1,1); MMA_MT(2,1); MMA_MT(3,1);
    }
#undef ISSUE
#undef LDSMB
#undef MMA_MT

    // ---------------- epilogue ----------------
#pragma unroll
    for (int mt = 0; mt < 4; mt++) {
#pragma unroll
        for (int nt = 0; nt < 8; nt++) {
            int lr = wm + mt*16 + gp;
            int c  = wn + nt*8 + 2*tg;
            int gn = n0 + c;
            float2 bb = *(const float2*)&Bias[(size_t)e*NDIM + gn];
#pragma unroll
            for (int half = 0; half < 2; half++) {
                int lrow = lr + half*8;
                int r = m0 + lrow;
                float v0 = D[mt][nt][half*2 + 0];
                float v1 = D[mt][nt][half*2 + 1];
                if (!IS2) {
                    if (r < kept) {
                        float o0 = silu_f(v0 + bb.x), o1 = silu_f(v1 + bb.y);
                        uint32_t hp;
                        asm("cvt.rn.f16x2.f32 %0, %1, %2;" : "=r"(hp) : "f"(o1), "f"(o0));
                        *(uint32_t*)&g_h[(size_t)(e*CAPP + r)*HID + gn] = hp;
                    }
                } else {
                    if (r < kept) {
                        int tok = stok[lrow];
                        float g = sgate[lrow];
                        atomicAdd(&Y[(size_t)tok*DM + gn    ], (v0 + bb.x) * g);
                        atomicAdd(&Y[(size_t)tok*DM + gn + 1], (v1 + bb.y) * g);
                    }
                }
            }
        }
    }
}

// ---------------- launch ----------------
extern "C" void kernel_launch(void* const* d_in, const int* in_sizes, int n_in,
                              void* d_out, int out_size) {
    const float* x  = (const float*)d_in[0];
    const float* Wr = (const float*)d_in[1];
    const float* br = (const float*)d_in[2];
    const float* W1 = (const float*)d_in[3];
    const float* b1 = (const float*)d_in[4];
    const float* W2 = (const float*)d_in[5];
    const float* b2 = (const float*)d_in[6];
    float* y = (float*)d_out;

    int N = in_sizes[0] / DM;
    if (N > MAXN) N = MAXN;
    int cap = (int)ceil(1.2 * (double)N / (double)E);
    if (cap > CAPP) cap = CAPP;
    int mt = (cap + BM - 1) / BM;

    cudaFuncSetAttribute(ffn_gemm_kernel<DM, HID, 0>,
                         cudaFuncAttributeMaxDynamicSharedMemorySize, SMEM_TOTAL);
    cudaFuncSetAttribute(ffn_gemm_kernel<HID, DM, 1>,
                         cudaFuncAttributeMaxDynamicSharedMemorySize, SMEM_TOTAL);

    cudaMemsetAsync(y, 0, (size_t)out_size * sizeof(float));
    zero_cnt_kernel<<<1, 32>>>();

    // weight conversion (independent of routing)
    __half* w1h; cudaGetSymbolAddress((void**)&w1h, g_w1h);
    __half* w2h; cudaGetSymbolAddress((void**)&w2h, g_w2h);
    const int n4 = (E*DM*HID) / 4;
    wconv_kernel<<<4096, 256>>>(W1, w1h, n4);
    wconv_kernel<<<4096, 256>>>(W2, w2h, n4);

    router_kernel<<<(N + 7) / 8, 256>>>(x, Wr, br, N);
    dim3 rg((2 * N + 255) / 256, E);
    rank_kernel<<<rg, 256>>>(cap);

    dim3 gg(CAPP / 8, E);
    gather_kernel<<<gg, 256>>>(x);

    __half* xgh; cudaGetSymbolAddress((void**)&xgh, g_xg);
    __half* hh;  cudaGetSymbolAddress((void**)&hh,  g_h);

    dim3 g1(HID / BN, mt, E);
    ffn_gemm_kernel<DM, HID, 0><<<g1, 256, SMEM_TOTAL>>>(xgh, w1h, b1, y);

    dim3 g2(DM / BN, mt, E);
    ffn_gemm_kernel<HID, DM, 1><<<g2, 256, SMEM_TOTAL>>>(hh, w2h, b2, y);
}

// round 9
// speedup vs baseline: 1.4739x; 1.4739x over previous
#include <cuda_runtime.h>
#include <cuda_fp16.h>
#include <math.h>
#include <stdint.h>

#define E 8
#define DM 1024
#define HID 4096
#define MAXN 16384
#define MAXM (MAXN*2)

#define BM 128
#define BN 256
#define BK 64
#define MTILES 20
#define CAPP (MTILES*BM)     // 2560 padded capacity rows per expert

// smem layout (bytes), per stage
#define A_STRIDE 144         // 64 fp16 data + pad, conflict-free LDSM
#define B_STRIDE 528         // 256 fp16 data + pad
#define OFF_A 0
#define OFF_B 18432
#define STAGE   52224
#define NSTAGE  3
#define SMEM_TOTAL (NSTAGE*STAGE + 1024)

// ---------------- device scratch ----------------
__device__ int    g_cnt[E];
__device__ int    g_bm[E*MAXM];
__device__ float  g_bg[E*MAXM];
__device__ int    g_disp_tok[E*CAPP];
__device__ float  g_disp_g[E*CAPP];
__device__ int    g_kept[E];
__device__ __half g_w1h[(size_t)E*DM*HID];
__device__ __half g_w2h[(size_t)E*HID*DM];
__device__ __half g_xg[(size_t)E*CAPP*DM];
__device__ __half g_h[(size_t)E*CAPP*HID];

// ---------------- helpers ----------------
__device__ __forceinline__ uint32_t smem_u32(const void* p) {
    uint32_t a;
    asm("{ .reg .u64 t; cvta.to.shared.u64 t, %1; cvt.u32.u64 %0, t; }" : "=r"(a) : "l"(p));
    return a;
}
#define CPA(s, g) \
    asm volatile("cp.async.cg.shared.global [%0], [%1], 16;" :: "r"(s), "l"(g))
#define CPA_COMMIT() asm volatile("cp.async.commit_group;" ::: "memory")
#define CPA_WAIT1()  asm volatile("cp.async.wait_group 1;" ::: "memory")

#define LDSM4(r0,r1,r2,r3,addr) \
    asm volatile("ldmatrix.sync.aligned.m8n8.x4.shared.b16 {%0,%1,%2,%3}, [%4];" \
        : "=r"(r0),"=r"(r1),"=r"(r2),"=r"(r3) : "r"(addr))
#define LDSM4T(r0,r1,r2,r3,addr) \
    asm volatile("ldmatrix.sync.aligned.m8n8.x4.trans.shared.b16 {%0,%1,%2,%3}, [%4];" \
        : "=r"(r0),"=r"(r1),"=r"(r2),"=r"(r3) : "r"(addr))

__device__ __forceinline__ void mma16816(float& d0, float& d1, float& d2, float& d3,
                                         uint32_t a0, uint32_t a1, uint32_t a2, uint32_t a3,
                                         uint32_t b0, uint32_t b1) {
    asm volatile("mma.sync.aligned.m16n8k16.row.col.f32.f16.f16.f32 "
                 "{%0,%1,%2,%3}, {%4,%5,%6,%7}, {%8,%9}, {%0,%1,%2,%3};\n"
                 : "+f"(d0), "+f"(d1), "+f"(d2), "+f"(d3)
                 : "r"(a0), "r"(a1), "r"(a2), "r"(a3), "r"(b0), "r"(b1));
}

__device__ __forceinline__ float silu_f(float z) { return z / (1.f + expf(-z)); }

// ---------------- small kernels ----------------
__global__ void zero_cnt_kernel() {
    if (threadIdx.x < E) g_cnt[threadIdx.x] = 0;
}

#define WRS 9   // padded stride (coprime with 32 -> conflict-free LDS)
__global__ void router_kernel(const float* __restrict__ x,
                              const float* __restrict__ Wr,
                              const float* __restrict__ br, int N) {
    __shared__ float sWr[DM*WRS];
    for (int i = threadIdx.x; i < DM*E; i += blockDim.x) {
        int d = i >> 3, e = i & 7;
        sWr[d*WRS + e] = Wr[i];
    }
    __syncthreads();
    int warp = threadIdx.x >> 5, lane = threadIdx.x & 31;
    int tok = blockIdx.x * 8 + warp;
    if (tok >= N) return;
    const float* xr = x + (size_t)tok * DM;
    float acc[E];
#pragma unroll
    for (int e = 0; e < E; e++) acc[e] = 0.f;
    for (int d = lane; d < DM; d += 32) {
        float xv = __ldg(xr + d);
        const float* w = sWr + d*WRS;
#pragma unroll
        for (int e = 0; e < E; e++) acc[e] += xv * w[e];
    }
#pragma unroll
    for (int e = 0; e < E; e++) {
#pragma unroll
        for (int o = 16; o > 0; o >>= 1) acc[e] += __shfl_xor_sync(0xffffffffu, acc[e], o);
    }
    if (lane == 0) {
        float l[E]; float mx = -1e30f;
#pragma unroll
        for (int e = 0; e < E; e++) { l[e] = acc[e] + __ldg(br + e); mx = fmaxf(mx, l[e]); }
        float s = 0.f;
#pragma unroll
        for (int e = 0; e < E; e++) { l[e] = expf(l[e] - mx); s += l[e]; }
        int i1 = 0; float p1 = -1.f;
#pragma unroll
        for (int e = 0; e < E; e++) { if (l[e] > p1) { p1 = l[e]; i1 = e; } }
        int i2 = -1; float p2 = -1.f;
#pragma unroll
        for (int e = 0; e < E; e++) { if (e != i1 && l[e] > p2) { p2 = l[e]; i2 = e; } }
        float inv = 1.f / s;
        int m0 = tok * 2;
        int pos = atomicAdd(&g_cnt[i1], 1);
        g_bm[i1*MAXM + pos] = m0;     g_bg[i1*MAXM + pos] = p1 * inv;
        pos = atomicAdd(&g_cnt[i2], 1);
        g_bm[i2*MAXM + pos] = m0 + 1; g_bg[i2*MAXM + pos] = p2 * inv;
    }
}

#define RCH 1024
__global__ void rank_kernel(int cap) {
    __shared__ float sg[RCH];
    __shared__ int   sm[RCH];
    int e = blockIdx.y;
    int cnt = g_cnt[e];
    if (blockIdx.x == 0 && threadIdx.x == 0) g_kept[e] = min(cnt, cap);
    int i = blockIdx.x * blockDim.x + threadIdx.x;
    bool has = (i < cnt);
    float gi = has ? g_bg[e*MAXM + i] : 0.f;
    int   mi = has ? g_bm[e*MAXM + i] : 0;
    int rank = 0;
    for (int j0 = 0; j0 < cnt; j0 += RCH) {
        int nj = min(RCH, cnt - j0);
        __syncthreads();
        for (int j = threadIdx.x; j < nj; j += blockDim.x) {
            sg[j] = g_bg[e*MAXM + j0 + j];
            sm[j] = g_bm[e*MAXM + j0 + j];
        }
        __syncthreads();
        if (has) {
            for (int j = 0; j < nj; j++) {
                float gj = sg[j]; int mj = sm[j];
                rank += (gj > gi) || (gj == gi && mj < mi);
            }
        }
    }
    if (has && rank < cap) {
        g_disp_tok[e*CAPP + rank] = mi >> 1;
        g_disp_g[e*CAPP + rank]   = gi;
    }
}

// weights fp32 -> fp16 (grid-stride over float4)
__global__ void wconv_kernel(const float* __restrict__ W, __half* __restrict__ out, int n4) {
    int i = blockIdx.x * blockDim.x + threadIdx.x;
    int stride = gridDim.x * blockDim.x;
    for (; i < n4; i += stride) {
        float4 v = __ldg(&((const float4*)W)[i]);
        uint32_t h0, h1;
        asm("cvt.rn.f16x2.f32 %0, %1, %2;" : "=r"(h0) : "f"(v.y), "f"(v.x));
        asm("cvt.rn.f16x2.f32 %0, %1, %2;" : "=r"(h1) : "f"(v.w), "f"(v.z));
        uint2 o; o.x = h0; o.y = h1;
        ((uint2*)out)[i] = o;
    }
}

// gather dispatched rows of x -> fp16 plane (zero-filled beyond kept)
__global__ void gather_kernel(const float* __restrict__ x) {
    int e = blockIdx.y;
    int warp = threadIdx.x >> 5, lane = threadIdx.x & 31;
    int r = blockIdx.x * 8 + warp;
    int kept = g_kept[e];
    bool v = r < kept;
    int tok = v ? g_disp_tok[e*CAPP + r] : 0;
    const float* src = x + (size_t)tok * DM;
    size_t dst = (size_t)(e*CAPP + r) * DM;
    for (int d = lane * 4; d < DM; d += 128) {
        float4 val = v ? __ldg((const float4*)(src + d)) : make_float4(0.f,0.f,0.f,0.f);
        uint32_t h0, h1;
        asm("cvt.rn.f16x2.f32 %0, %1, %2;" : "=r"(h0) : "f"(val.y), "f"(val.x));
        asm("cvt.rn.f16x2.f32 %0, %1, %2;" : "=r"(h1) : "f"(val.w), "f"(val.z));
        uint2 oh; oh.x = h0; oh.y = h1;
        *(uint2*)&g_xg[dst + d] = oh;
    }
}

// ---------------- GEMM (fp16 HMMA, BK=64, 3-stage cp.async, frag double-buffer) --------
// IS2==0: A = g_xg [*,DM],  B = g_w1h [DM,HID], epi: silu(+b1) -> g_h
// IS2==1: A = g_h [*,HID],  B = g_w2h [HID,DM], epi: (+b2)*g -> atomicAdd Y
template <int KDIM, int NDIM, int IS2>
__global__ void __launch_bounds__(256, 1)
ffn_gemm_kernel(const __half* __restrict__ A, const __half* __restrict__ W,
                const float* __restrict__ Bias, float* __restrict__ Y) {
    extern __shared__ __align__(1024) char smem[];
    const uint32_t su = smem_u32(smem);
    const int tid = threadIdx.x, warp = tid >> 5, lane = tid & 31;
    const int e = blockIdx.z, m0 = blockIdx.y * BM, n0 = blockIdx.x * BN;
    const int kept = g_kept[e];

    int*   stok  = (int*)(smem + NSTAGE*STAGE);
    float* sgate = (float*)(smem + NSTAGE*STAGE + 512);
    if (tid < BM) {
        int r = m0 + tid; bool v = r < kept;
        stok[tid]  = v ? g_disp_tok[e*CAPP + r] : 0;
        sgate[tid] = v ? g_disp_g[e*CAPP + r]   : 0.f;
    }

    // warp tiling: 2 warps along M (64 rows), 4 along N (64 cols)
    const int wm = (warp >> 2) * 64;
    const int wn = (warp & 3) * 64;
    const int q = lane >> 3, rr = lane & 7;
    const int gp = lane >> 2, tg = lane & 3;

    const uint32_t a_base = (uint32_t)((wm + rr + (q & 1) * 8) * A_STRIDE + (q >> 1) * 16);
    const uint32_t b_base = (uint32_t)((rr + (q & 1) * 8) * B_STRIDE + (wn + (q >> 1) * 8) * 2);

    // producer (cp.async) mapping — BK=64
    const int a_row = tid >> 1, a_kh = tid & 1;        // row, k-half (32 elems each)
    const int b_row = tid >> 5, b_nc = tid & 31;       // rows b_row + 8j, 16B chunk b_nc
    const uint32_t a_cs = (uint32_t)(a_row * A_STRIDE + a_kh * 64);
    const uint32_t b_cs = (uint32_t)(b_row * B_STRIDE + b_nc * 16);
    const __half* At = A + (size_t)(e*CAPP + m0 + a_row)*KDIM + a_kh*32;
    const __half* Bt = W + (size_t)e*KDIM*NDIM + (size_t)b_row*NDIM + n0 + b_nc*8;

    float D[4][8][4];
#pragma unroll
    for (int a = 0; a < 4; a++)
#pragma unroll
        for (int b = 0; b < 8; b++)
#pragma unroll
            for (int c = 0; c < 4; c++) D[a][b][c] = 0.f;

    uint32_t Af[2][4][4], Bf[2][8][2];
    const int KCH = KDIM / BK;

#define ISSUE(KT, SB) do {                                                     \
    const __half* _a = At + (size_t)(KT)*BK;                                   \
    _Pragma("unroll")                                                          \
    for (int j = 0; j < 4; j++)                                                \
        CPA((SB) + OFF_A + a_cs + j*16, _a + j*8);                             \
    const __half* _b = Bt + (size_t)(KT)*BK*NDIM;                              \
    _Pragma("unroll")                                                          \
    for (int j = 0; j < 8; j++)                                                \
        CPA((SB) + OFF_B + b_cs + j*8*B_STRIDE, _b + (size_t)j*8*NDIM);        \
} while (0)

#define LDFRAG(buf, kk) do {                                                   \
    const uint32_t _ab = sb + OFF_A + a_base + (kk)*32;                        \
    _Pragma("unroll")                                                          \
    for (int mt = 0; mt < 4; mt++)                                             \
        LDSM4(Af[buf][mt][0],Af[buf][mt][1],Af[buf][mt][2],Af[buf][mt][3],     \
              _ab + mt*16*A_STRIDE);                                           \
    const uint32_t _bb = sb + OFF_B + b_base + (kk)*16*B_STRIDE;               \
    _Pragma("unroll")                                                          \
    for (int ntp = 0; ntp < 4; ntp++)                                          \
        LDSM4T(Bf[buf][ntp*2][0],Bf[buf][ntp*2][1],                            \
               Bf[buf][ntp*2+1][0],Bf[buf][ntp*2+1][1], _bb + ntp*32);         \
} while (0)

#define MMA_ALL(buf) do {                                                      \
    _Pragma("unroll")                                                          \
    for (int mt = 0; mt < 4; mt++)                                             \
        _Pragma("unroll")                                                      \
        for (int nt = 0; nt < 8; nt++)                                         \
            mma16816(D[mt][nt][0],D[mt][nt][1],D[mt][nt][2],D[mt][nt][3],      \
                     Af[buf][mt][0],Af[buf][mt][1],Af[buf][mt][2],Af[buf][mt][3],\
                     Bf[buf][nt][0],Bf[buf][nt][1]);                           \
} while (0)

    // prologue: 2 stages in flight
    ISSUE(0, su + 0*STAGE); CPA_COMMIT();
    ISSUE(1, su + 1*STAGE); CPA_COMMIT();

#pragma unroll 1
    for (int kt = 0; kt < KCH; kt++) {
        CPA_WAIT1();
        __syncthreads();
        const uint32_t sb = su + (uint32_t)(kt % NSTAGE) * STAGE;
        if (kt + 2 < KCH) ISSUE(kt + 2, su + (uint32_t)((kt + 2) % NSTAGE) * STAGE);
        CPA_COMMIT();
        LDFRAG(0, 0);
#pragma unroll
        for (int kk = 0; kk < 4; kk++) {
            if (kk < 3) LDFRAG((kk + 1) & 1, kk + 1);
            MMA_ALL(kk & 1);
        }
        __syncthreads();
    }
#undef ISSUE
#undef LDFRAG
#undef MMA_ALL

    // ---------------- epilogue ----------------
#pragma unroll
    for (int mt = 0; mt < 4; mt++) {
#pragma unroll
        for (int nt = 0; nt < 8; nt++) {
            int lr = wm + mt*16 + gp;
            int c  = wn + nt*8 + 2*tg;
            int gn = n0 + c;
            float2 bb = *(const float2*)&Bias[(size_t)e*NDIM + gn];
#pragma unroll
            for (int half = 0; half < 2; half++) {
                int lrow = lr + half*8;
                int r = m0 + lrow;
                float v0 = D[mt][nt][half*2 + 0];
                float v1 = D[mt][nt][half*2 + 1];
                if (!IS2) {
                    if (r < kept) {
                        float o0 = silu_f(v0 + bb.x), o1 = silu_f(v1 + bb.y);
                        uint32_t hp;
                        asm("cvt.rn.f16x2.f32 %0, %1, %2;" : "=r"(hp) : "f"(o1), "f"(o0));
                        *(uint32_t*)&g_h[(size_t)(e*CAPP + r)*HID + gn] = hp;
                    }
                } else {
                    if (r < kept) {
                        int tok = stok[lrow];
                        float g = sgate[lrow];
                        atomicAdd(&Y[(size_t)tok*DM + gn    ], (v0 + bb.x) * g);
                        atomicAdd(&Y[(size_t)tok*DM + gn + 1], (v1 + bb.y) * g);
                    }
                }
            }
        }
    }
}

// ---------------- launch ----------------
extern "C" void kernel_launch(void* const* d_in, const int* in_sizes, int n_in,
                              void* d_out, int out_size) {
    const float* x  = (const float*)d_in[0];
    const float* Wr = (const float*)d_in[1];
    const float* br = (const float*)d_in[2];
    const float* W1 = (const float*)d_in[3];
    const float* b1 = (const float*)d_in[4];
    const float* W2 = (const float*)d_in[5];
    const float* b2 = (const float*)d_in[6];
    float* y = (float*)d_out;

    int N = in_sizes[0] / DM;
    if (N > MAXN) N = MAXN;
    int cap = (int)ceil(1.2 * (double)N / (double)E);
    if (cap > CAPP) cap = CAPP;
    int mt = (cap + BM - 1) / BM;

    cudaFuncSetAttribute(ffn_gemm_kernel<DM, HID, 0>,
                         cudaFuncAttributeMaxDynamicSharedMemorySize, SMEM_TOTAL);
    cudaFuncSetAttribute(ffn_gemm_kernel<HID, DM, 1>,
                         cudaFuncAttributeMaxDynamicSharedMemorySize, SMEM_TOTAL);

    cudaMemsetAsync(y, 0, (size_t)out_size * sizeof(float));
    zero_cnt_kernel<<<1, 32>>>();

    // weight conversion (independent of routing)
    __half* w1h; cudaGetSymbolAddress((void**)&w1h, g_w1h);
    __half* w2h; cudaGetSymbolAddress((void**)&w2h, g_w2h);
    const int n4 = (E*DM*HID) / 4;
    wconv_kernel<<<4096, 256>>>(W1, w1h, n4);
    wconv_kernel<<<4096, 256>>>(W2, w2h, n4);

    router_kernel<<<(N + 7) / 8, 256>>>(x, Wr, br, N);
    dim3 rg((2 * N + 255) / 256, E);
    rank_kernel<<<rg, 256>>>(cap);

    dim3 gg(CAPP / 8, E);
    gather_kernel<<<gg, 256>>>(x);

    __half* xgh; cudaGetSymbolAddress((void**)&xgh, g_xg);
    __half* hh;  cudaGetSymbolAddress((void**)&hh,  g_h);

    dim3 g1(HID / BN, mt, E);
    ffn_gemm_kernel<DM, HID, 0><<<g1, 256, SMEM_TOTAL>>>(xgh, w1h, b1, y);

    dim3 g2(DM / BN, mt, E);
    ffn_gemm_kernel<HID, DM, 1><<<g2, 256, SMEM_TOTAL>>>(hh, w2h, b2, y);
}

// round 10
// speedup vs baseline: 1.4769x; 1.0020x over previous
#include <cuda_runtime.h>
#include <cuda_fp16.h>
#include <math.h>
#include <stdint.h>

#define E 8
#define DM 1024
#define HID 4096
#define MAXN 16384
#define MAXM (MAXN*2)

#define BM 128
#define BN 256
#define BK 64
#define MTILES 20
#define CAPP (MTILES*BM)     // 2560 padded capacity rows per expert

// smem layout (bytes), per stage
#define A_STRIDE 144         // 64 fp16 data + pad, conflict-free LDSM
#define B_STRIDE 528         // 256 fp16 data + pad
#define OFF_A 0
#define OFF_B 18432
#define STAGE   52224
#define NSTAGE  3
#define SMEM_TOTAL (NSTAGE*STAGE + 1024)

// ---------------- device scratch ----------------
__device__ int    g_cnt[E];
__device__ int    g_bm[E*MAXM];
__device__ float  g_bg[E*MAXM];
__device__ int    g_disp_tok[E*CAPP];
__device__ float  g_disp_g[E*CAPP];
__device__ int    g_kept[E];
__device__ __half g_w1h[(size_t)E*DM*HID];
__device__ __half g_w2h[(size_t)E*HID*DM];
__device__ __half g_xg[(size_t)E*CAPP*DM];
__device__ __half g_h[(size_t)E*CAPP*HID];

// ---------------- helpers ----------------
__device__ __forceinline__ uint32_t smem_u32(const void* p) {
    uint32_t a;
    asm("{ .reg .u64 t; cvta.to.shared.u64 t, %1; cvt.u32.u64 %0, t; }" : "=r"(a) : "l"(p));
    return a;
}
#define CPA(s, g) \
    asm volatile("cp.async.cg.shared.global [%0], [%1], 16;" :: "r"(s), "l"(g))
#define CPA_COMMIT() asm volatile("cp.async.commit_group;" ::: "memory")
#define CPA_WAIT1()  asm volatile("cp.async.wait_group 1;" ::: "memory")

#define LDSM4(r0,r1,r2,r3,addr) \
    asm volatile("ldmatrix.sync.aligned.m8n8.x4.shared.b16 {%0,%1,%2,%3}, [%4];" \
        : "=r"(r0),"=r"(r1),"=r"(r2),"=r"(r3) : "r"(addr))
#define LDSM4T(r0,r1,r2,r3,addr) \
    asm volatile("ldmatrix.sync.aligned.m8n8.x4.trans.shared.b16 {%0,%1,%2,%3}, [%4];" \
        : "=r"(r0),"=r"(r1),"=r"(r2),"=r"(r3) : "r"(addr))

__device__ __forceinline__ void mma16816(float& d0, float& d1, float& d2, float& d3,
                                         uint32_t a0, uint32_t a1, uint32_t a2, uint32_t a3,
                                         uint32_t b0, uint32_t b1) {
    asm volatile("mma.sync.aligned.m16n8k16.row.col.f32.f16.f16.f32 "
                 "{%0,%1,%2,%3}, {%4,%5,%6,%7}, {%8,%9}, {%0,%1,%2,%3};\n"
                 : "+f"(d0), "+f"(d1), "+f"(d2), "+f"(d3)
                 : "r"(a0), "r"(a1), "r"(a2), "r"(a3), "r"(b0), "r"(b1));
}

__device__ __forceinline__ float silu_f(float z) { return z / (1.f + expf(-z)); }

// ---------------- small kernels ----------------
__global__ void zero_cnt_kernel() {
    if (threadIdx.x < E) g_cnt[threadIdx.x] = 0;
}

#define WRS 9   // padded stride (coprime with 32 -> conflict-free LDS)
__global__ void router_kernel(const float* __restrict__ x,
                              const float* __restrict__ Wr,
                              const float* __restrict__ br, int N) {
    __shared__ float sWr[DM*WRS];
    for (int i = threadIdx.x; i < DM*E; i += blockDim.x) {
        int d = i >> 3, e = i & 7;
        sWr[d*WRS + e] = Wr[i];
    }
    __syncthreads();
    int warp = threadIdx.x >> 5, lane = threadIdx.x & 31;
    int tok = blockIdx.x * 8 + warp;
    if (tok >= N) return;
    const float* xr = x + (size_t)tok * DM;
    float acc[E];
#pragma unroll
    for (int e = 0; e < E; e++) acc[e] = 0.f;
    for (int d = lane; d < DM; d += 32) {
        float xv = __ldg(xr + d);
        const float* w = sWr + d*WRS;
#pragma unroll
        for (int e = 0; e < E; e++) acc[e] += xv * w[e];
    }
#pragma unroll
    for (int e = 0; e < E; e++) {
#pragma unroll
        for (int o = 16; o > 0; o >>= 1) acc[e] += __shfl_xor_sync(0xffffffffu, acc[e], o);
    }
    if (lane == 0) {
        float l[E]; float mx = -1e30f;
#pragma unroll
        for (int e = 0; e < E; e++) { l[e] = acc[e] + __ldg(br + e); mx = fmaxf(mx, l[e]); }
        float s = 0.f;
#pragma unroll
        for (int e = 0; e < E; e++) { l[e] = expf(l[e] - mx); s += l[e]; }
        int i1 = 0; float p1 = -1.f;
#pragma unroll
        for (int e = 0; e < E; e++) { if (l[e] > p1) { p1 = l[e]; i1 = e; } }
        int i2 = -1; float p2 = -1.f;
#pragma unroll
        for (int e = 0; e < E; e++) { if (e != i1 && l[e] > p2) { p2 = l[e]; i2 = e; } }
        float inv = 1.f / s;
        int m0 = tok * 2;
        int pos = atomicAdd(&g_cnt[i1], 1);
        g_bm[i1*MAXM + pos] = m0;     g_bg[i1*MAXM + pos] = p1 * inv;
        pos = atomicAdd(&g_cnt[i2], 1);
        g_bm[i2*MAXM + pos] = m0 + 1; g_bg[i2*MAXM + pos] = p2 * inv;
    }
}

#define RCH 1024
__global__ void rank_kernel(int cap) {
    __shared__ float sg[RCH];
    __shared__ int   sm[RCH];
    int e = blockIdx.y;
    int cnt = g_cnt[e];
    if (blockIdx.x == 0 && threadIdx.x == 0) g_kept[e] = min(cnt, cap);
    int i = blockIdx.x * blockDim.x + threadIdx.x;
    bool has = (i < cnt);
    float gi = has ? g_bg[e*MAXM + i] : 0.f;
    int   mi = has ? g_bm[e*MAXM + i] : 0;
    int rank = 0;
    for (int j0 = 0; j0 < cnt; j0 += RCH) {
        int nj = min(RCH, cnt - j0);
        __syncthreads();
        for (int j = threadIdx.x; j < nj; j += blockDim.x) {
            sg[j] = g_bg[e*MAXM + j0 + j];
            sm[j] = g_bm[e*MAXM + j0 + j];
        }
        __syncthreads();
        if (has) {
            for (int j = 0; j < nj; j++) {
                float gj = sg[j]; int mj = sm[j];
                rank += (gj > gi) || (gj == gi && mj < mi);
            }
        }
    }
    if (has && rank < cap) {
        g_disp_tok[e*CAPP + rank] = mi >> 1;
        g_disp_g[e*CAPP + rank]   = gi;
    }
}

// weights fp32 -> fp16 (grid-stride over float4)
__global__ void wconv_kernel(const float* __restrict__ W, __half* __restrict__ out, int n4) {
    int i = blockIdx.x * blockDim.x + threadIdx.x;
    int stride = gridDim.x * blockDim.x;
    for (; i < n4; i += stride) {
        float4 v = __ldg(&((const float4*)W)[i]);
        uint32_t h0, h1;
        asm("cvt.rn.f16x2.f32 %0, %1, %2;" : "=r"(h0) : "f"(v.y), "f"(v.x));
        asm("cvt.rn.f16x2.f32 %0, %1, %2;" : "=r"(h1) : "f"(v.w), "f"(v.z));
        uint2 o; o.x = h0; o.y = h1;
        ((uint2*)out)[i] = o;
    }
}

// gather dispatched rows of x -> fp16 plane (zero-filled beyond kept)
__global__ void gather_kernel(const float* __restrict__ x) {
    int e = blockIdx.y;
    int warp = threadIdx.x >> 5, lane = threadIdx.x & 31;
    int r = blockIdx.x * 8 + warp;
    int kept = g_kept[e];
    bool v = r < kept;
    int tok = v ? g_disp_tok[e*CAPP + r] : 0;
    const float* src = x + (size_t)tok * DM;
    size_t dst = (size_t)(e*CAPP + r) * DM;
    for (int d = lane * 4; d < DM; d += 128) {
        float4 val = v ? __ldg((const float4*)(src + d)) : make_float4(0.f,0.f,0.f,0.f);
        uint32_t h0, h1;
        asm("cvt.rn.f16x2.f32 %0, %1, %2;" : "=r"(h0) : "f"(val.y), "f"(val.x));
        asm("cvt.rn.f16x2.f32 %0, %1, %2;" : "=r"(h1) : "f"(val.w), "f"(val.z));
        uint2 oh; oh.x = h0; oh.y = h1;
        *(uint2*)&g_xg[dst + d] = oh;
    }
}

// ---------------- GEMM (fp16 HMMA, BK=64, 3-stage cp.async, frag double-buffer) --------
// IS2==0: A = g_xg [*,DM],  B = g_w1h [DM,HID], epi: silu(+b1) -> g_h
// IS2==1: A = g_h [*,HID],  B = g_w2h [HID,DM], epi: (+b2)*g -> atomicAdd Y
template <int KDIM, int NDIM, int IS2>
__global__ void __launch_bounds__(256, 1)
ffn_gemm_kernel(const __half* __restrict__ A, const __half* __restrict__ W,
                const float* __restrict__ Bias, float* __restrict__ Y) {
    extern __shared__ __align__(1024) char smem[];
    const uint32_t su = smem_u32(smem);
    const int tid = threadIdx.x, warp = tid >> 5, lane = tid & 31;
    const int e = blockIdx.z, m0 = blockIdx.y * BM, n0 = blockIdx.x * BN;
    const int kept = g_kept[e];

    int*   stok  = (int*)(smem + NSTAGE*STAGE);
    float* sgate = (float*)(smem + NSTAGE*STAGE + 512);
    if (tid < BM) {
        int r = m0 + tid; bool v = r < kept;
        stok[tid]  = v ? g_disp_tok[e*CAPP + r] : 0;
        sgate[tid] = v ? g_disp_g[e*CAPP + r]   : 0.f;
    }

    // warp tiling: 2 warps along M (64 rows), 4 along N (64 cols)
    const int wm = (warp >> 2) * 64;
    const int wn = (warp & 3) * 64;
    const int q = lane >> 3, rr = lane & 7;
    const int gp = lane >> 2, tg = lane & 3;

    const uint32_t a_base = (uint32_t)((wm + rr + (q & 1) * 8) * A_STRIDE + (q >> 1) * 16);
    const uint32_t b_base = (uint32_t)((rr + (q & 1) * 8) * B_STRIDE + (wn + (q >> 1) * 8) * 2);

    // producer (cp.async) mapping — BK=64
    const int a_row = tid >> 1, a_kh = tid & 1;        // row, k-half (32 elems each)
    const int b_row = tid >> 5, b_nc = tid & 31;       // rows b_row + 8j, 16B chunk b_nc
    const uint32_t a_cs = (uint32_t)(a_row * A_STRIDE + a_kh * 64);
    const uint32_t b_cs = (uint32_t)(b_row * B_STRIDE + b_nc * 16);
    const __half* At = A + (size_t)(e*CAPP + m0 + a_row)*KDIM + a_kh*32;
    const __half* Bt = W + (size_t)e*KDIM*NDIM + (size_t)b_row*NDIM + n0 + b_nc*8;

    float D[4][8][4];
#pragma unroll
    for (int a = 0; a < 4; a++)
#pragma unroll
        for (int b = 0; b < 8; b++)
#pragma unroll
            for (int c = 0; c < 4; c++) D[a][b][c] = 0.f;

    uint32_t Af[2][4][4], Bf[2][8][2];
    const int KCH = KDIM / BK;

#define ISSUE(KT, SB) do {                                                     \
    const __half* _a = At + (size_t)(KT)*BK;                                   \
    _Pragma("unroll")                                                          \
    for (int j = 0; j < 4; j++)                                                \
        CPA((SB) + OFF_A + a_cs + j*16, _a + j*8);                             \
    const __half* _b = Bt + (size_t)(KT)*BK*NDIM;                              \
    _Pragma("unroll")                                                          \
    for (int j = 0; j < 8; j++)                                                \
        CPA((SB) + OFF_B + b_cs + j*8*B_STRIDE, _b + (size_t)j*8*NDIM);        \
} while (0)

#define LDFRAG(buf, kk) do {                                                   \
    const uint32_t _ab = sb + OFF_A + a_base + (kk)*32;                        \
    _Pragma("unroll")                                                          \
    for (int mt = 0; mt < 4; mt++)                                             \
        LDSM4(Af[buf][mt][0],Af[buf][mt][1],Af[buf][mt][2],Af[buf][mt][3],     \
              _ab + mt*16*A_STRIDE);                                           \
    const uint32_t _bb = sb + OFF_B + b_base + (kk)*16*B_STRIDE;               \
    _Pragma("unroll")                                                          \
    for (int ntp = 0; ntp < 4; ntp++)                                          \
        LDSM4T(Bf[buf][ntp*2][0],Bf[buf][ntp*2][1],                            \
               Bf[buf][ntp*2+1][0],Bf[buf][ntp*2+1][1], _bb + ntp*32);         \
} while (0)

#define MMA_ALL(buf) do {                                                      \
    _Pragma("unroll")                                                          \
    for (int mt = 0; mt < 4; mt++)                                             \
        _Pragma("unroll")                                                      \
        for (int nt = 0; nt < 8; nt++)                                         \
            mma16816(D[mt][nt][0],D[mt][nt][1],D[mt][nt][2],D[mt][nt][3],      \
                     Af[buf][mt][0],Af[buf][mt][1],Af[buf][mt][2],Af[buf][mt][3],\
                     Bf[buf][nt][0],Bf[buf][nt][1]);                           \
} while (0)

    // prologue: 2 stages in flight
    ISSUE(0, su + 0*STAGE); CPA_COMMIT();
    ISSUE(1, su + 1*STAGE); CPA_COMMIT();

#pragma unroll 1
    for (int kt = 0; kt < KCH; kt++) {
        CPA_WAIT1();
        __syncthreads();
        const uint32_t sb = su + (uint32_t)(kt % NSTAGE) * STAGE;
        if (kt + 2 < KCH) ISSUE(kt + 2, su + (uint32_t)((kt + 2) % NSTAGE) * STAGE);
        CPA_COMMIT();
        LDFRAG(0, 0);
#pragma unroll
        for (int kk = 0; kk < 4; kk++) {
            if (kk < 3) LDFRAG((kk + 1) & 1, kk + 1);
            MMA_ALL(kk & 1);
        }
        __syncthreads();
    }
#undef ISSUE
#undef LDFRAG
#undef MMA_ALL

    // ---------------- epilogue ----------------
#pragma unroll
    for (int mt = 0; mt < 4; mt++) {
#pragma unroll
        for (int nt = 0; nt < 8; nt++) {
            int lr = wm + mt*16 + gp;
            int c  = wn + nt*8 + 2*tg;
            int gn = n0 + c;
            float2 bb = *(const float2*)&Bias[(size_t)e*NDIM + gn];
#pragma unroll
            for (int half = 0; half < 2; half++) {
                int lrow = lr + half*8;
                int r = m0 + lrow;
                float v0 = D[mt][nt][half*2 + 0];
                float v1 = D[mt][nt][half*2 + 1];
                if (!IS2) {
                    if (r < kept) {
                        float o0 = silu_f(v0 + bb.x), o1 = silu_f(v1 + bb.y);
                        uint32_t hp;
                        asm("cvt.rn.f16x2.f32 %0, %1, %2;" : "=r"(hp) : "f"(o1), "f"(o0));
                        *(uint32_t*)&g_h[(size_t)(e*CAPP + r)*HID + gn] = hp;
                    }
                } else {
                    if (r < kept) {
                        int tok = stok[lrow];
                        float g = sgate[lrow];
                        atomicAdd(&Y[(size_t)tok*DM + gn    ], (v0 + bb.x) * g);
                        atomicAdd(&Y[(size_t)tok*DM + gn + 1], (v1 + bb.y) * g);
                    }
                }
            }
        }
    }
}

// ---------------- launch ----------------
extern "C" void kernel_launch(void* const* d_in, const int* in_sizes, int n_in,
                              void* d_out, int out_size) {
    const float* x  = (const float*)d_in[0];
    const float* Wr = (const float*)d_in[1];
    const float* br = (const float*)d_in[2];
    const float* W1 = (const float*)d_in[3];
    const float* b1 = (const float*)d_in[4];
    const float* W2 = (const float*)d_in[5];
    const float* b2 = (const float*)d_in[6];
    float* y = (float*)d_out;

    int N = in_sizes[0] / DM;
    if (N > MAXN) N = MAXN;
    int cap = (int)ceil(1.2 * (double)N / (double)E);
    if (cap > CAPP) cap = CAPP;
    int mt = (cap + BM - 1) / BM;

    cudaFuncSetAttribute(ffn_gemm_kernel<DM, HID, 0>,
                         cudaFuncAttributeMaxDynamicSharedMemorySize, SMEM_TOTAL);
    cudaFuncSetAttribute(ffn_gemm_kernel<HID, DM, 1>,
                         cudaFuncAttributeMaxDynamicSharedMemorySize, SMEM_TOTAL);

    cudaMemsetAsync(y, 0, (size_t)out_size * sizeof(float));
    zero_cnt_kernel<<<1, 32>>>();

    // weight conversion (independent of routing)
    __half* w1h; cudaGetSymbolAddress((void**)&w1h, g_w1h);
    __half* w2h; cudaGetSymbolAddress((void**)&w2h, g_w2h);
    const int n4 = (E*DM*HID) / 4;
    wconv_kernel<<<4096, 256>>>(W1, w1h, n4);
    wconv_kernel<<<4096, 256>>>(W2, w2h, n4);

    router_kernel<<<(N + 7) / 8, 256>>>(x, Wr, br, N);
    dim3 rg((2 * N + 255) / 256, E);
    rank_kernel<<<rg, 256>>>(cap);

    dim3 gg(CAPP / 8, E);
    gather_kernel<<<gg, 256>>>(x);

    __half* xgh; cudaGetSymbolAddress((void**)&xgh, g_xg);
    __half* hh;  cudaGetSymbolAddress((void**)&hh,  g_h);

    dim3 g1(HID / BN, mt, E);
    ffn_gemm_kernel<DM, HID, 0><<<g1, 256, SMEM_TOTAL>>>(xgh, w1h, b1, y);

    dim3 g2(DM / BN, mt, E);
    ffn_gemm_kernel<HID, DM, 1><<<g2, 256, SMEM_TOTAL>>>(hh, w2h, b2, y);
}